// round 2
// baseline (speedup 1.0000x reference)
#include <cuda_runtime.h>
#include <cstdint>

#define H       512
#define HEADS   8
#define DK      64
#define NCLASS  4
#define VOCAB   5000
#define LW      32
#define NLEAF   20000
#define NPAR    20000
#define NTOT    40000
#define DEG     4
#define NLAYER  5
#define HP      (H + 8)      // padded pitch for bank-conflict relief
#define NB_RED  125
#define RED_CHUNK 160        // 125*160 = 20000

// ---- scratch (static device globals; no allocation at runtime) ----
__device__ float g_nodeh[(size_t)NTOT * H];     // 82 MB: h for every node
__device__ float g_xepar[(size_t)NPAR * H];     // xe for parents
__device__ float g_EbuT[(size_t)VOCAB * H];     // transposed embedding
__device__ int   g_flags[NPAR];                 // parent-ready flags
__device__ float g_pmax[NB_RED * H];            // partial max

// ------------------------------------------------------------------
__global__ void k_zero_flags() {
    int i = blockIdx.x * blockDim.x + threadIdx.x;
    if (i < NPAR) g_flags[i] = 0;
}

// E_bu [H, VOCAB] -> g_EbuT [VOCAB, H]
__global__ void k_transpose(const float* __restrict__ E) {
    __shared__ float t[32][33];
    int x = blockIdx.x * 32 + threadIdx.x;          // vocab
    int y0 = blockIdx.y * 32;                        // h
#pragma unroll
    for (int j = 0; j < 32; j += 8) {
        int y = y0 + threadIdx.y + j;
        t[threadIdx.y + j][threadIdx.x] = (x < VOCAB) ? E[(size_t)y * VOCAB + x] : 0.f;
    }
    __syncthreads();
    int xo = blockIdx.y * 32 + threadIdx.x;          // h
    int yo0 = blockIdx.x * 32;                       // vocab
#pragma unroll
    for (int j = 0; j < 32; j += 8) {
        int yo = yo0 + threadIdx.y + j;
        if (yo < VOCAB) g_EbuT[(size_t)yo * H + xo] = t[threadIdx.x][threadIdx.y + j];
    }
}

// xe[n] = sum_l w[n,l] * EbuT[idx[n,l], :]; leaves -> node_h, parents -> xepar
__global__ void k_embed(const float* __restrict__ xw, const int* __restrict__ xi) {
    int n = blockIdx.x;
    int tid = threadIdx.x;                  // 128 threads, float4 each
    __shared__ float s_w[LW];
    __shared__ int   s_i[LW];
    if (tid < LW) { s_w[tid] = xw[n * LW + tid]; s_i[tid] = xi[n * LW + tid]; }
    __syncthreads();
    float4 acc = make_float4(0.f, 0.f, 0.f, 0.f);
#pragma unroll 8
    for (int l = 0; l < LW; l++) {
        const float4* row = (const float4*)(g_EbuT + (size_t)s_i[l] * H);
        float4 e = row[tid];
        float w = s_w[l];
        acc.x += w * e.x; acc.y += w * e.y; acc.z += w * e.z; acc.w += w * e.w;
    }
    float4* dst = (n < NLEAF) ? (float4*)(g_nodeh + (size_t)n * H)
                              : (float4*)(g_xepar + (size_t)(n - NLEAF) * H);
    dst[tid] = acc;
}

__device__ __forceinline__ float sigmoidf_(float x) { return 1.f / (1.f + __expf(-x)); }

// Persistent dataflow kernel over parents.
__global__ void __launch_bounds__(512, 2) k_tree(
    const int* __restrict__ tree,
    const float* __restrict__ Wz, const float* __restrict__ Uz, const float* __restrict__ bz,
    const float* __restrict__ Wr, const float* __restrict__ Ur, const float* __restrict__ br,
    const float* __restrict__ Wh, const float* __restrict__ Uh, const float* __restrict__ bh)
{
    __shared__ float s_h[2][DEG][HP];
    __shared__ float s_xe[H];
    __shared__ float s_mem[H];
    __shared__ float s_mr[H];
    __shared__ float s_sc[HEADS][DEG][DEG];
    __shared__ float s_p[HEADS][DEG][DEG];
    __shared__ int   s_child[DEG];

    int tid = threadIdx.x;

    for (int p = blockIdx.x; p < NPAR; p += gridDim.x) {
        if (tid < DEG) s_child[tid] = tree[p * DEG + tid];
        __syncthreads();

        // wait for parent-children readiness (ids strictly < NLEAF+p => no cycles)
        if (tid < DEG) {
            int c = s_child[tid];
            if (c >= NLEAF) {
                while (atomicAdd(&g_flags[c - NLEAF], 0) == 0) __nanosleep(100);
                __threadfence();   // acquire
            }
        }
        __syncthreads();

        // gather children h (L2 loads; L1 may be stale across SMs)
#pragma unroll
        for (int k = 0; k < DEG; k++) {
            int c = s_child[k];
            s_h[0][k][tid] = (c > -1) ? __ldcg(g_nodeh + (size_t)c * H + tid) : 0.f;
        }
        s_xe[tid] = g_xepar[(size_t)p * H + tid];
        __syncthreads();

        // 5 layers of 4-token / 8-head self-attention (q=k=v=h)
        int cur = 0;
        for (int layer = 0; layer < NLAYER; layer++) {
            if (tid < HEADS * DEG * DEG) {
                int head = tid >> 4, q = (tid >> 2) & 3, kk = tid & 3;
                const float* hq = &s_h[cur][q][head * DK];
                const float* hk = &s_h[cur][kk][head * DK];
                float s = 0.f;
#pragma unroll
                for (int d = 0; d < DK; d++) s += hq[d] * hk[d];
                s *= 0.125f;                        // 1/sqrt(64)
                if (s_child[kk] <= -1) s = -1e9f;   // key mask (matches reference)
                s_sc[head][q][kk] = s;
            }
            __syncthreads();
            if (tid < HEADS * DEG) {
                int head = tid >> 2, q = tid & 3;
                float m = s_sc[head][q][0];
#pragma unroll
                for (int kk = 1; kk < DEG; kk++) m = fmaxf(m, s_sc[head][q][kk]);
                float e[DEG]; float sum = 0.f;
#pragma unroll
                for (int kk = 0; kk < DEG; kk++) { e[kk] = __expf(s_sc[head][q][kk] - m); sum += e[kk]; }
                float inv = 1.f / sum;
#pragma unroll
                for (int kk = 0; kk < DEG; kk++) s_p[head][q][kk] = e[kk] * inv;
            }
            __syncthreads();
            {
                int head = tid >> 6, d = tid & 63;
                int col = head * DK + d;
                float v0 = s_h[cur][0][col], v1 = s_h[cur][1][col];
                float v2 = s_h[cur][2][col], v3 = s_h[cur][3][col];
#pragma unroll
                for (int q = 0; q < DEG; q++) {
                    s_h[cur ^ 1][q][col] = s_p[head][q][0] * v0 + s_p[head][q][1] * v1
                                         + s_p[head][q][2] * v2 + s_p[head][q][3] * v3;
                }
            }
            __syncthreads();
            cur ^= 1;
        }

        // memory = masked mean over children
        {
            int cnt = 0;
#pragma unroll
            for (int k = 0; k < DEG; k++) cnt += (s_child[k] > -1);
            float denom = (float)max(cnt, 1);
            float m = 0.f;
#pragma unroll
            for (int k = 0; k < DEG; k++) if (s_child[k] > -1) m += s_h[cur][k][tid];
            s_mem[tid] = m / denom;
        }
        __syncthreads();

        // GRU: stage 1 (z, r, Wh·xe), fp32 matvecs, each thread owns one output dim
        float az = bz[tid], ar = br[tid], ac = bh[tid];
        {
            const float4* wz = (const float4*)(Wz + (size_t)tid * H);
            const float4* uz = (const float4*)(Uz + (size_t)tid * H);
            const float4* wr = (const float4*)(Wr + (size_t)tid * H);
            const float4* ur = (const float4*)(Ur + (size_t)tid * H);
            const float4* wh = (const float4*)(Wh + (size_t)tid * H);
            const float4* xv = (const float4*)s_xe;
            const float4* mv = (const float4*)s_mem;
#pragma unroll 2
            for (int j = 0; j < H / 4; j++) {
                float4 x = xv[j], m = mv[j];
                float4 a = wz[j]; az += a.x*x.x + a.y*x.y + a.z*x.z + a.w*x.w;
                float4 b = uz[j]; az += b.x*m.x + b.y*m.y + b.z*m.z + b.w*m.w;
                float4 cR = wr[j]; ar += cR.x*x.x + cR.y*x.y + cR.z*x.z + cR.w*x.w;
                float4 dR = ur[j]; ar += dR.x*m.x + dR.y*m.y + dR.z*m.z + dR.w*m.w;
                float4 eH = wh[j]; ac += eH.x*x.x + eH.y*x.y + eH.z*x.z + eH.w*x.w;
            }
        }
        float z = sigmoidf_(az), r = sigmoidf_(ar);
        s_mr[tid] = s_mem[tid] * r;
        __syncthreads();
        // stage 2: Uh·(mem*r)
        {
            const float4* uh = (const float4*)(Uh + (size_t)tid * H);
            const float4* mr = (const float4*)s_mr;
#pragma unroll 2
            for (int j = 0; j < H / 4; j++) {
                float4 a = uh[j], b = mr[j];
                ac += a.x*b.x + a.y*b.y + a.z*b.z + a.w*b.w;
            }
        }
        float c = tanhf(ac);
        float ph = z * s_mem[tid] + (1.f - z) * c;
        __stcg(g_nodeh + (size_t)(NLEAF + p) * H + tid, ph);
        __syncthreads();
        if (tid == 0) {
            __threadfence();            // release
            atomicExch(&g_flags[p], 1);
        }
        // s_child/s_xe overwritten next iter only after the barrier above
    }
}

// partial column-max over parents
__global__ void k_redmax() {
    int tid = threadIdx.x;
    int b = blockIdx.x;
    const float* base = g_nodeh + (size_t)NLEAF * H;
    float m = -3.4e38f;
    for (int p = b * RED_CHUNK; p < (b + 1) * RED_CHUNK; p++)
        m = fmaxf(m, base[(size_t)p * H + tid]);
    g_pmax[b * H + tid] = m;
}

__global__ void k_final(const float* __restrict__ Wo, const float* __restrict__ bo,
                        float* __restrict__ out) {
    __shared__ float s_f[H];
    __shared__ float s_logit[NCLASS];
    int tid = threadIdx.x;  // 512
    float m = g_pmax[tid];
    for (int b = 1; b < NB_RED; b++) m = fmaxf(m, g_pmax[b * H + tid]);
    s_f[tid] = m;
    __syncthreads();
    int w = tid >> 5, lane = tid & 31;
    if (w < NCLASS) {
        float acc = 0.f;
        for (int j = lane; j < H; j += 32) acc += Wo[w * H + j] * s_f[j];
#pragma unroll
        for (int off = 16; off; off >>= 1) acc += __shfl_down_sync(0xffffffffu, acc, off);
        if (lane == 0) s_logit[w] = acc + bo[w];
    }
    __syncthreads();
    if (tid == 0) {
        float mx = s_logit[0];
        for (int i = 1; i < NCLASS; i++) mx = fmaxf(mx, s_logit[i]);
        float e[NCLASS], s = 0.f;
        for (int i = 0; i < NCLASS; i++) { e[i] = __expf(s_logit[i] - mx); s += e[i]; }
        for (int i = 0; i < NCLASS; i++) out[i] = e[i] / s;
    }
}

extern "C" void kernel_launch(void* const* d_in, const int* in_sizes, int n_in,
                              void* d_out, int out_size) {
    const float* x_word  = (const float*)d_in[0];
    const int*   x_index = (const int*)  d_in[1];
    const int*   tree    = (const int*)  d_in[2];
    const float* E_bu    = (const float*)d_in[3];
    const float* W_z = (const float*)d_in[4];
    const float* U_z = (const float*)d_in[5];
    const float* b_z = (const float*)d_in[6];
    const float* W_r = (const float*)d_in[7];
    const float* U_r = (const float*)d_in[8];
    const float* b_r = (const float*)d_in[9];
    const float* W_h = (const float*)d_in[10];
    const float* U_h = (const float*)d_in[11];
    const float* b_h = (const float*)d_in[12];
    const float* W_out = (const float*)d_in[13];
    const float* b_out = (const float*)d_in[14];
    float* out = (float*)d_out;

    // guaranteed-co-resident persistent grid (computed once; pure constant)
    static int nb_tree = 0;
    if (nb_tree == 0) {
        int dev = 0; cudaGetDevice(&dev);
        int nsm = 0; cudaDeviceGetAttribute(&nsm, cudaDevAttrMultiProcessorCount, dev);
        int perSM = 0;
        cudaOccupancyMaxActiveBlocksPerMultiprocessor(&perSM, k_tree, 512, 0);
        if (perSM < 1) perSM = 1;
        long nb = (long)nsm * perSM;
        if (nb > NPAR) nb = NPAR;
        nb_tree = (int)nb;
    }

    k_zero_flags<<<(NPAR + 255) / 256, 256>>>();
    dim3 tb(32, 8);
    dim3 tg((VOCAB + 31) / 32, H / 32);
    k_transpose<<<tg, tb>>>(E_bu);
    k_embed<<<NTOT, 128>>>(x_word, x_index);
    k_tree<<<nb_tree, 512>>>(tree, W_z, U_z, b_z, W_r, U_r, b_r, W_h, U_h, b_h);
    k_redmax<<<NB_RED, H>>>();
    k_final<<<1, H>>>(W_out, b_out, out);
}

// round 4
// speedup vs baseline: 6.9731x; 6.9731x over previous
#include <cuda_runtime.h>
#include <cstdint>

#define H 512
#define DK 64
#define NCLASS 4
#define VOCAB 5000
#define LW 32
#define NLEAF 20000
#define NPAR 20000
#define NTOT 40000
#define DEG 4
#define NLAYER 5
#define LMAX 256
#define SMALL 16
#define NB_RED 125
#define RED_CHUNK 160

__device__ float g_nodeh[(size_t)NTOT * H];
__device__ float g_xepar[(size_t)NPAR * H];
__device__ float g_EbuT[(size_t)VOCAB * H];
__device__ float g_gz0[(size_t)NPAR * H];
__device__ float g_gr0[(size_t)NPAR * H];
__device__ float g_gh0[(size_t)NPAR * H];
__device__ float g_memv[(size_t)NPAR * H];
__device__ float g_mrv[(size_t)NPAR * H];
__device__ float g_zv[(size_t)NPAR * H];
__device__ int g_lvl[NPAR];
__device__ int g_hist[LMAX], g_lstart[LMAX], g_lofs[LMAX], g_order[NPAR];
__device__ int g_nlev, g_barcnt;
__device__ volatile int g_barsense;
__device__ float g_pmax[NB_RED * H];

__device__ __forceinline__ float sigf(float x) { return 1.f / (1.f + __expf(-x)); }

// ----------------------------------------------------------------------
__global__ void k_init() {
    int i = blockIdx.x * blockDim.x + threadIdx.x;
    if (i < NPAR) g_lvl[i] = -1;
    if (i < LMAX) g_hist[i] = 0;
    if (i == 0) { g_barcnt = 0; g_barsense = 0; }
}

__global__ void k_transpose(const float* __restrict__ E) {
    __shared__ float t[32][33];
    int x = blockIdx.x * 32 + threadIdx.x;
    int y0 = blockIdx.y * 32;
#pragma unroll
    for (int j = 0; j < 32; j += 8) {
        int y = y0 + threadIdx.y + j;
        t[threadIdx.y + j][threadIdx.x] = (x < VOCAB) ? E[(size_t)y * VOCAB + x] : 0.f;
    }
    __syncthreads();
    int xo = blockIdx.y * 32 + threadIdx.x;
    int yo0 = blockIdx.x * 32;
#pragma unroll
    for (int j = 0; j < 32; j += 8) {
        int yo = yo0 + threadIdx.y + j;
        if (yo < VOCAB) g_EbuT[(size_t)yo * H + xo] = t[threadIdx.x][threadIdx.y + j];
    }
}

__global__ void k_embed(const float* __restrict__ xw, const int* __restrict__ xi) {
    int n = blockIdx.x;
    int tid = threadIdx.x;   // 128
    __shared__ float s_w[LW];
    __shared__ int   s_i[LW];
    if (tid < LW) { s_w[tid] = xw[n * LW + tid]; s_i[tid] = xi[n * LW + tid]; }
    __syncthreads();
    float4 acc = make_float4(0.f, 0.f, 0.f, 0.f);
#pragma unroll 8
    for (int l = 0; l < LW; l++) {
        float4 e = ((const float4*)(g_EbuT + (size_t)s_i[l] * H))[tid];
        float w = s_w[l];
        acc.x += w * e.x; acc.y += w * e.y; acc.z += w * e.z; acc.w += w * e.w;
    }
    float4* dst = (n < NLEAF) ? (float4*)(g_nodeh + (size_t)n * H)
                              : (float4*)(g_xepar + (size_t)(n - NLEAF) * H);
    dst[tid] = acc;
}

__global__ void k_plevel(const int* __restrict__ tree) {
    int p = blockIdx.x * blockDim.x + threadIdx.x;
    if (p >= NPAR) return;
    int lv = 0;
#pragma unroll
    for (int k = 0; k < DEG; k++) {
        int c = tree[p * DEG + k];
        if (c >= NLEAF) {
            int v;
            while ((v = atomicAdd(&g_lvl[c - NLEAF], 0)) < 0) __nanosleep(40);
            lv = max(lv, v + 1);
        }
    }
    if (lv > LMAX - 1) lv = LMAX - 1;
    atomicExch(&g_lvl[p], lv);
}

__global__ void k_hist() {
    int p = blockIdx.x * blockDim.x + threadIdx.x;
    if (p < NPAR) atomicAdd(&g_hist[g_lvl[p]], 1);
}

__global__ void k_scan() {
    int acc = 0, nl = 1;
    for (int i = 0; i < LMAX; i++) {
        g_lstart[i] = acc; g_lofs[i] = acc;
        acc += g_hist[i];
        if (g_hist[i] > 0) nl = i + 1;
    }
    g_nlev = nl;
}

__global__ void k_scatter() {
    int p = blockIdx.x * blockDim.x + threadIdx.x;
    if (p < NPAR) g_order[atomicAdd(&g_lofs[g_lvl[p]], 1)] = p;
}

// ------------------- pre-GEMM: out[i,:] = W * xe[order[i]] + b -------------------
// BM=128, BN=64, BK=16, 256 thr, thread tile 8x4
__global__ void __launch_bounds__(256) k_pregemm(
    const float* __restrict__ Wz, const float* __restrict__ bz,
    const float* __restrict__ Wr, const float* __restrict__ br,
    const float* __restrict__ Wh, const float* __restrict__ bh)
{
    __shared__ float sX[16 * 132];
    __shared__ float sW[16 * 68];
    __shared__ int s_ord[128];
    int sel = blockIdx.z;
    const float* W    = sel == 0 ? Wz : sel == 1 ? Wr : Wh;
    const float* bias = sel == 0 ? bz : sel == 1 ? br : bh;
    float* out        = sel == 0 ? g_gz0 : sel == 1 ? g_gr0 : g_gh0;
    int m0 = blockIdx.x * 128, n0 = blockIdx.y * 64;
    int t = threadIdx.x;
    if (t < 128) s_ord[t] = g_order[min(m0 + t, NPAR - 1)];
    __syncthreads();
    int ty = t >> 4, tx = t & 15;
    float acc[8][4];
#pragma unroll
    for (int i = 0; i < 8; i++)
#pragma unroll
        for (int j = 0; j < 4; j++) acc[i][j] = 0.f;
    int lrow = t >> 1, lko = (t & 1) * 8;
    int wn = t >> 2, wko = (t & 3) * 4;
    for (int kc = 0; kc < H; kc += 16) {
        const float* xr = g_xepar + (size_t)s_ord[lrow] * H + kc + lko;
        float4 x0 = *(const float4*)xr, x1 = *(const float4*)(xr + 4);
        sX[(lko + 0) * 132 + lrow] = x0.x; sX[(lko + 1) * 132 + lrow] = x0.y;
        sX[(lko + 2) * 132 + lrow] = x0.z; sX[(lko + 3) * 132 + lrow] = x0.w;
        sX[(lko + 4) * 132 + lrow] = x1.x; sX[(lko + 5) * 132 + lrow] = x1.y;
        sX[(lko + 6) * 132 + lrow] = x1.z; sX[(lko + 7) * 132 + lrow] = x1.w;
        float4 w0 = *(const float4*)(W + (size_t)(n0 + wn) * H + kc + wko);
        sW[(wko + 0) * 68 + wn] = w0.x; sW[(wko + 1) * 68 + wn] = w0.y;
        sW[(wko + 2) * 68 + wn] = w0.z; sW[(wko + 3) * 68 + wn] = w0.w;
        __syncthreads();
#pragma unroll
        for (int kk = 0; kk < 16; kk++) {
            float a[8], b[4];
#pragma unroll
            for (int i = 0; i < 8; i++) a[i] = sX[kk * 132 + ty * 8 + i];
#pragma unroll
            for (int j = 0; j < 4; j++) b[j] = sW[kk * 68 + tx * 4 + j];
#pragma unroll
            for (int i = 0; i < 8; i++)
#pragma unroll
                for (int j = 0; j < 4; j++) acc[i][j] += a[i] * b[j];
        }
        __syncthreads();
    }
#pragma unroll
    for (int i = 0; i < 8; i++) {
        int m = m0 + ty * 8 + i;
        if (m >= NPAR) continue;
        float* dst = out + (size_t)m * H + n0 + tx * 4;
#pragma unroll
        for (int j = 0; j < 4; j++) dst[j] = acc[i][j] + bias[n0 + tx * 4 + j];
    }
}

// ------------------- persistent level kernel -------------------
__device__ __forceinline__ void gridbar(int nb, int& sense) {
    __syncthreads();
    if (threadIdx.x == 0) {
        sense ^= 1;
        __threadfence();
        if (atomicAdd(&g_barcnt, 1) == nb - 1) {
            atomicExch(&g_barcnt, 0);
            __threadfence();
            g_barsense = sense;
        } else {
            while (g_barsense != sense) __nanosleep(64);
        }
    }
    __syncthreads();
}

#define AH(buf,k,head) (((buf)*4+(k))*8+(head))*65

__device__ int attn_core(int p, const int* __restrict__ tree, float* SBUF,
                         int* s_child, float* s_sc, float* s_p) {
    int tid = threadIdx.x;
    __syncthreads();
    if (tid < DEG) s_child[tid] = tree[p * DEG + tid];
    __syncthreads();
#pragma unroll
    for (int j = 0; j < 8; j++) {
        int idx = tid + j * 256;
        int k = idx >> 9, col = idx & 511, head = col >> 6, d = col & 63;
        int c = s_child[k];
        SBUF[AH(0, k, head) + d] = (c > -1) ? __ldcg(&g_nodeh[(size_t)c * H + col]) : 0.f;
    }
    __syncthreads();
    int cur = 0;
    for (int layer = 0; layer < NLAYER; layer++) {
        if (tid < 128) {
            int head = tid >> 4, q = (tid >> 2) & 3, kk = tid & 3;
            const float* hq = &SBUF[AH(cur, q, head)];
            const float* hk = &SBUF[AH(cur, kk, head)];
            float s = 0.f;
#pragma unroll
            for (int d = 0; d < DK; d++) s += hq[d] * hk[d];
            s *= 0.125f;
            if (s_child[kk] <= -1) s = -1e9f;
            s_sc[(head * 4 + q) * 4 + kk] = s;
        }
        __syncthreads();
        if (tid < 32) {
            int head = tid >> 2, q = tid & 3;
            const float* r = &s_sc[(head * 4 + q) * 4];
            float m = fmaxf(fmaxf(r[0], r[1]), fmaxf(r[2], r[3]));
            float e0 = __expf(r[0] - m), e1 = __expf(r[1] - m);
            float e2 = __expf(r[2] - m), e3 = __expf(r[3] - m);
            float inv = 1.f / (e0 + e1 + e2 + e3);
            float* pr = &s_p[(head * 4 + q) * 4];
            pr[0] = e0 * inv; pr[1] = e1 * inv; pr[2] = e2 * inv; pr[3] = e3 * inv;
        }
        __syncthreads();
        int nxt = cur ^ 1;
#pragma unroll
        for (int j = 0; j < 2; j++) {
            int col = tid + j * 256, head = col >> 6, d = col & 63;
            float v0 = SBUF[AH(cur, 0, head) + d];
            float v1 = SBUF[AH(cur, 1, head) + d];
            float v2 = SBUF[AH(cur, 2, head) + d];
            float v3 = SBUF[AH(cur, 3, head) + d];
#pragma unroll
            for (int q = 0; q < 4; q++) {
                const float* pr = &s_p[(head * 4 + q) * 4];
                SBUF[AH(nxt, q, head) + d] = pr[0] * v0 + pr[1] * v1 + pr[2] * v2 + pr[3] * v3;
            }
        }
        __syncthreads();
        cur = nxt;
    }
    return cur;
}

__device__ void phaseA(int row, const int* __restrict__ tree, float* SBUF,
                       int* s_child, float* s_sc, float* s_p) {
    int tid = threadIdx.x;
    int p = g_order[row];
    int cur = attn_core(p, tree, SBUF, s_child, s_sc, s_p);
    int cc = (s_child[0] > -1) + (s_child[1] > -1) + (s_child[2] > -1) + (s_child[3] > -1);
    float denom = (float)max(cc, 1);
#pragma unroll
    for (int j = 0; j < 2; j++) {
        int col = tid + j * 256, head = col >> 6, d = col & 63;
        float m = 0.f;
#pragma unroll
        for (int k = 0; k < DEG; k++)
            if (s_child[k] > -1) m += SBUF[AH(cur, k, head) + d];
        __stcg(&g_memv[(size_t)row * H + col], m / denom);
    }
}

__device__ void fused_small(int row, const int* __restrict__ tree,
                            const float* __restrict__ Uz, const float* __restrict__ Ur,
                            const float* __restrict__ Uh,
                            float* SBUF, int* s_child, float* s_sc, float* s_p) {
    int tid = threadIdx.x;
    int p = g_order[row];
    int cur = attn_core(p, tree, SBUF, s_child, s_sc, s_p);
    float* s_mem = SBUF + 4160;
    float* s_mr  = SBUF + 4672;
    float* s_z   = SBUF + 5184;
    int cc = (s_child[0] > -1) + (s_child[1] > -1) + (s_child[2] > -1) + (s_child[3] > -1);
    float denom = (float)max(cc, 1);
#pragma unroll
    for (int j = 0; j < 2; j++) {
        int col = tid + j * 256, head = col >> 6, d = col & 63;
        float m = 0.f;
#pragma unroll
        for (int k = 0; k < DEG; k++)
            if (s_child[k] > -1) m += SBUF[AH(cur, k, head) + d];
        s_mem[col] = m / denom;
    }
    __syncthreads();
    int warp = tid >> 5, lane = tid & 31;
    const float4* mv = (const float4*)s_mem;
    for (int task = warp; task < 1024; task += 8) {
        int d = task & 511;
        const float4* ur = (const float4*)((task < 512 ? Uz : Ur) + (size_t)d * H);
        float acc = 0.f;
#pragma unroll
        for (int i = 0; i < 4; i++) {
            float4 a = __ldg(&ur[lane + i * 32]);
            float4 b = mv[lane + i * 32];
            acc += a.x * b.x + a.y * b.y + a.z * b.z + a.w * b.w;
        }
#pragma unroll
        for (int o = 16; o; o >>= 1) acc += __shfl_down_sync(0xffffffffu, acc, o);
        if (lane == 0) {
            if (task < 512) s_z[d] = sigf(__ldg(&g_gz0[(size_t)row * H + d]) + acc);
            else            s_mr[d] = s_mem[d] * sigf(__ldg(&g_gr0[(size_t)row * H + d]) + acc);
        }
    }
    __syncthreads();
    const float4* mrv4 = (const float4*)s_mr;
    for (int d = warp; d < 512; d += 8) {
        const float4* uh = (const float4*)(Uh + (size_t)d * H);
        float acc = 0.f;
#pragma unroll
        for (int i = 0; i < 4; i++) {
            float4 a = __ldg(&uh[lane + i * 32]);
            float4 b = mrv4[lane + i * 32];
            acc += a.x * b.x + a.y * b.y + a.z * b.z + a.w * b.w;
        }
#pragma unroll
        for (int o = 16; o; o >>= 1) acc += __shfl_down_sync(0xffffffffu, acc, o);
        if (lane == 0) {
            float c = tanhf(__ldg(&g_gh0[(size_t)row * H + d]) + acc);
            float z = s_z[d];
            SBUF[d] = z * s_mem[d] + (1.f - z) * c;
        }
    }
    __syncthreads();
#pragma unroll
    for (int j = 0; j < 2; j++) {
        int col = tid + j * 256;
        __stcg(&g_nodeh[(size_t)(NLEAF + p) * H + col], SBUF[col]);
    }
}

// gate GEMM tile: BM=32 rows, BN=64 dims, both Uz and Ur
__device__ void phaseB(int start, int cnt, int t,
                       const float* __restrict__ Uz, const float* __restrict__ Ur,
                       float* SBUF) {
    int tid = threadIdx.x;
    int m0 = (t >> 3) * 32, n0 = (t & 7) * 64;
    float* sA  = SBUF;
    float* sWz = SBUF + 1056;
    float* sWr = SBUF + 3136;
    int ty = tid >> 4, tx = tid & 15;
    int am = tid >> 3, ak = (tid & 7) * 4;
    int wn = tid >> 2, wk = (tid & 3) * 8;
    float az[2][4], ar[2][4];
#pragma unroll
    for (int i = 0; i < 2; i++)
#pragma unroll
        for (int j = 0; j < 4; j++) { az[i][j] = 0.f; ar[i][j] = 0.f; }
    __syncthreads();
    for (int kc = 0; kc < H; kc += 32) {
        int rrow = start + ((m0 + am < cnt) ? m0 + am : 0);
        float4 a = __ldcg((const float4*)&g_memv[(size_t)rrow * H + kc + ak]);
        sA[(ak + 0) * 33 + am] = a.x; sA[(ak + 1) * 33 + am] = a.y;
        sA[(ak + 2) * 33 + am] = a.z; sA[(ak + 3) * 33 + am] = a.w;
        const float* wz = Uz + (size_t)(n0 + wn) * H + kc + wk;
        float4 z0 = *(const float4*)wz, z1 = *(const float4*)(wz + 4);
        sWz[(wk + 0) * 65 + wn] = z0.x; sWz[(wk + 1) * 65 + wn] = z0.y;
        sWz[(wk + 2) * 65 + wn] = z0.z; sWz[(wk + 3) * 65 + wn] = z0.w;
        sWz[(wk + 4) * 65 + wn] = z1.x; sWz[(wk + 5) * 65 + wn] = z1.y;
        sWz[(wk + 6) * 65 + wn] = z1.z; sWz[(wk + 7) * 65 + wn] = z1.w;
        const float* wr = Ur + (size_t)(n0 + wn) * H + kc + wk;
        float4 r0 = *(const float4*)wr, r1 = *(const float4*)(wr + 4);
        sWr[(wk + 0) * 65 + wn] = r0.x; sWr[(wk + 1) * 65 + wn] = r0.y;
        sWr[(wk + 2) * 65 + wn] = r0.z; sWr[(wk + 3) * 65 + wn] = r0.w;
        sWr[(wk + 4) * 65 + wn] = r1.x; sWr[(wk + 5) * 65 + wn] = r1.y;
        sWr[(wk + 6) * 65 + wn] = r1.z; sWr[(wk + 7) * 65 + wn] = r1.w;
        __syncthreads();
#pragma unroll
        for (int kk = 0; kk < 32; kk++) {
            float a0 = sA[kk * 33 + ty * 2], a1 = sA[kk * 33 + ty * 2 + 1];
#pragma unroll
            for (int n = 0; n < 4; n++) {
                float bz = sWz[kk * 65 + tx * 4 + n];
                float br = sWr[kk * 65 + tx * 4 + n];
                az[0][n] += a0 * bz; az[1][n] += a1 * bz;
                ar[0][n] += a0 * br; ar[1][n] += a1 * br;
            }
        }
        __syncthreads();
    }
#pragma unroll
    for (int mi = 0; mi < 2; mi++) {
        int m = m0 + ty * 2 + mi;
        if (m >= cnt) continue;
        size_t base = (size_t)(start + m) * H + n0 + tx * 4;
#pragma unroll
        for (int n = 0; n < 4; n++) {
            float z = sigf(__ldg(&g_gz0[base + n]) + az[mi][n]);
            float r = sigf(__ldg(&g_gr0[base + n]) + ar[mi][n]);
            float mem = __ldcg(&g_memv[base + n]);
            __stcg(&g_zv[base + n], z);
            __stcg(&g_mrv[base + n], mem * r);
        }
    }
}

__device__ void phaseC(int start, int cnt, int t,
                       const float* __restrict__ Uh, float* SBUF, int* s_pid) {
    int tid = threadIdx.x;
    int m0 = (t >> 3) * 32, n0 = (t & 7) * 64;
    float* sA = SBUF;
    float* sW = SBUF + 1056;
    int ty = tid >> 4, tx = tid & 15;
    int am = tid >> 3, ak = (tid & 7) * 4;
    int wn = tid >> 2, wk = (tid & 3) * 8;
    float ah[2][4];
#pragma unroll
    for (int i = 0; i < 2; i++)
#pragma unroll
        for (int j = 0; j < 4; j++) ah[i][j] = 0.f;
    __syncthreads();
    if (tid < 32) s_pid[tid] = g_order[start + min(m0 + tid, cnt - 1)];
    for (int kc = 0; kc < H; kc += 32) {
        int rrow = start + ((m0 + am < cnt) ? m0 + am : 0);
        float4 a = __ldcg((const float4*)&g_mrv[(size_t)rrow * H + kc + ak]);
        sA[(ak + 0) * 33 + am] = a.x; sA[(ak + 1) * 33 + am] = a.y;
        sA[(ak + 2) * 33 + am] = a.z; sA[(ak + 3) * 33 + am] = a.w;
        const float* wh = Uh + (size_t)(n0 + wn) * H + kc + wk;
        float4 h0 = *(const float4*)wh, h1 = *(const float4*)(wh + 4);
        sW[(wk + 0) * 65 + wn] = h0.x; sW[(wk + 1) * 65 + wn] = h0.y;
        sW[(wk + 2) * 65 + wn] = h0.z; sW[(wk + 3) * 65 + wn] = h0.w;
        sW[(wk + 4) * 65 + wn] = h1.x; sW[(wk + 5) * 65 + wn] = h1.y;
        sW[(wk + 6) * 65 + wn] = h1.z; sW[(wk + 7) * 65 + wn] = h1.w;
        __syncthreads();
#pragma unroll
        for (int kk = 0; kk < 32; kk++) {
            float a0 = sA[kk * 33 + ty * 2], a1 = sA[kk * 33 + ty * 2 + 1];
#pragma unroll
            for (int n = 0; n < 4; n++) {
                float b = sW[kk * 65 + tx * 4 + n];
                ah[0][n] += a0 * b; ah[1][n] += a1 * b;
            }
        }
        __syncthreads();
    }
#pragma unroll
    for (int mi = 0; mi < 2; mi++) {
        int m = m0 + ty * 2 + mi;
        if (m >= cnt) continue;
        int p = s_pid[ty * 2 + mi];
        size_t base = (size_t)(start + m) * H + n0 + tx * 4;
#pragma unroll
        for (int n = 0; n < 4; n++) {
            float c = tanhf(__ldg(&g_gh0[base + n]) + ah[mi][n]);
            float z = __ldcg(&g_zv[base + n]);
            float mem = __ldcg(&g_memv[base + n]);
            __stcg(&g_nodeh[(size_t)(NLEAF + p) * H + n0 + tx * 4 + n],
                   z * mem + (1.f - z) * c);
        }
    }
}

__global__ void __launch_bounds__(256) k_main(
    const int* __restrict__ tree,
    const float* __restrict__ Uz, const float* __restrict__ Ur,
    const float* __restrict__ Uh)
{
    __shared__ float SBUF[5696];
    __shared__ float s_sc[128], s_p[128];
    __shared__ int s_child[DEG], s_pid[32];
    int nb = gridDim.x;
    int sense = 0;
    int nlev = g_nlev;
    for (int l = 0; l < nlev; l++) {
        int start = g_lstart[l], cnt = g_hist[l];
        if (cnt <= SMALL) {
            for (int j = blockIdx.x; j < cnt; j += nb)
                fused_small(start + j, tree, Uz, Ur, Uh, SBUF, s_child, s_sc, s_p);
            gridbar(nb, sense);
        } else {
            for (int j = blockIdx.x; j < cnt; j += nb)
                phaseA(start + j, tree, SBUF, s_child, s_sc, s_p);
            gridbar(nb, sense);
            int nt = ((cnt + 31) >> 5) * 8;
            for (int t = blockIdx.x; t < nt; t += nb)
                phaseB(start, cnt, t, Uz, Ur, SBUF);
            gridbar(nb, sense);
            for (int t = blockIdx.x; t < nt; t += nb)
                phaseC(start, cnt, t, Uh, SBUF, s_pid);
            gridbar(nb, sense);
        }
    }
}

__global__ void k_redmax() {
    int tid = threadIdx.x;
    int b = blockIdx.x;
    const float* base = g_nodeh + (size_t)NLEAF * H;
    float m = -3.4e38f;
    for (int p = b * RED_CHUNK; p < (b + 1) * RED_CHUNK; p++)
        m = fmaxf(m, base[(size_t)p * H + tid]);
    g_pmax[b * H + tid] = m;
}

__global__ void k_final(const float* __restrict__ Wo, const float* __restrict__ bo,
                        float* __restrict__ out) {
    __shared__ float s_f[H];
    __shared__ float s_logit[NCLASS];
    int tid = threadIdx.x;   // 512
    float m = g_pmax[tid];
    for (int b = 1; b < NB_RED; b++) m = fmaxf(m, g_pmax[b * H + tid]);
    s_f[tid] = m;
    __syncthreads();
    int w = tid >> 5, lane = tid & 31;
    if (w < NCLASS) {
        float acc = 0.f;
        for (int j = lane; j < H; j += 32) acc += Wo[w * H + j] * s_f[j];
#pragma unroll
        for (int o = 16; o; o >>= 1) acc += __shfl_down_sync(0xffffffffu, acc, o);
        if (lane == 0) s_logit[w] = acc + bo[w];
    }
    __syncthreads();
    if (tid == 0) {
        float mx = s_logit[0];
        for (int i = 1; i < NCLASS; i++) mx = fmaxf(mx, s_logit[i]);
        float e[NCLASS], s = 0.f;
        for (int i = 0; i < NCLASS; i++) { e[i] = __expf(s_logit[i] - mx); s += e[i]; }
        for (int i = 0; i < NCLASS; i++) out[i] = e[i] / s;
    }
}

extern "C" void kernel_launch(void* const* d_in, const int* in_sizes, int n_in,
                              void* d_out, int out_size) {
    const float* x_word  = (const float*)d_in[0];
    const int*   x_index = (const int*)  d_in[1];
    const int*   tree    = (const int*)  d_in[2];
    const float* E_bu    = (const float*)d_in[3];
    const float* W_z = (const float*)d_in[4];
    const float* U_z = (const float*)d_in[5];
    const float* b_z = (const float*)d_in[6];
    const float* W_r = (const float*)d_in[7];
    const float* U_r = (const float*)d_in[8];
    const float* b_r = (const float*)d_in[9];
    const float* W_h = (const float*)d_in[10];
    const float* U_h = (const float*)d_in[11];
    const float* b_h = (const float*)d_in[12];
    const float* W_out = (const float*)d_in[13];
    const float* b_out = (const float*)d_in[14];
    float* out = (float*)d_out;

    static int nb_main = 0;
    if (nb_main == 0) {
        int dev = 0; cudaGetDevice(&dev);
        int nsm = 0; cudaDeviceGetAttribute(&nsm, cudaDevAttrMultiProcessorCount, dev);
        int perSM = 0;
        cudaOccupancyMaxActiveBlocksPerMultiprocessor(&perSM, k_main, 256, 0);
        if (perSM < 1) perSM = 1;
        nb_main = nsm * perSM;
    }

    k_init<<<(NPAR + 255) / 256, 256>>>();
    dim3 tb(32, 8), tg((VOCAB + 31) / 32, H / 32);
    k_transpose<<<tg, tb>>>(E_bu);
    k_embed<<<NTOT, 128>>>(x_word, x_index);
    k_plevel<<<(NPAR + 255) / 256, 256>>>(tree);
    k_hist<<<(NPAR + 255) / 256, 256>>>();
    k_scan<<<1, 1>>>();
    k_scatter<<<(NPAR + 255) / 256, 256>>>();
    k_pregemm<<<dim3((NPAR + 127) / 128, H / 64, 3), 256>>>(W_z, b_z, W_r, b_r, W_h, b_h);
    k_main<<<nb_main, 256>>>(tree, U_z, U_r, U_h);
    k_redmax<<<NB_RED, H>>>();
    k_final<<<1, H>>>(W_out, b_out, out);
}

// round 5
// speedup vs baseline: 7.6594x; 1.0984x over previous
#include <cuda_runtime.h>
#include <cstdint>

#define H 512
#define DK 64
#define NCLASS 4
#define VOCAB 5000
#define LW 32
#define NLEAF 20000
#define NPAR 20000
#define NTOT 40000
#define DEG 4
#define NLAYER 5
#define LMAX 256
#define NB_RED 125
#define RED_CHUNK 160

__device__ float g_nodeh[(size_t)NTOT * H];
__device__ float g_xepar[(size_t)NPAR * H];
__device__ float g_EbuT[(size_t)VOCAB * H];
__device__ float g_gz0[(size_t)NPAR * H];   // parent-id indexed
__device__ float g_gr0[(size_t)NPAR * H];
__device__ float g_gh0[(size_t)NPAR * H];
__device__ float g_memv[(size_t)NPAR * H];  // row (order) indexed
__device__ float g_mrv[(size_t)NPAR * H];
__device__ float g_zv[(size_t)NPAR * H];
__device__ int g_lvl[NPAR];
__device__ int g_hist[LMAX], g_lstart[LMAX], g_lofs[LMAX], g_order[NPAR];
__device__ int g_nlev, g_barcnt;
__device__ volatile int g_barsense;
__device__ float g_pmax[NB_RED * H];

__device__ __forceinline__ float sigf(float x) { return 1.f / (1.f + __expf(-x)); }

// ---------------- launch 1: transpose + init ----------------
__global__ void k_setup(const float* __restrict__ E) {
    __shared__ float t[32][33];
    int x = blockIdx.x * 32 + threadIdx.x;
    int y0 = blockIdx.y * 32;
#pragma unroll
    for (int j = 0; j < 32; j += 8) {
        int y = y0 + threadIdx.y + j;
        t[threadIdx.y + j][threadIdx.x] = (x < VOCAB) ? E[(size_t)y * VOCAB + x] : 0.f;
    }
    __syncthreads();
    int xo = blockIdx.y * 32 + threadIdx.x;
    int yo0 = blockIdx.x * 32;
#pragma unroll
    for (int j = 0; j < 32; j += 8) {
        int yo = yo0 + threadIdx.y + j;
        if (yo < VOCAB) g_EbuT[(size_t)yo * H + xo] = t[threadIdx.x][threadIdx.y + j];
    }
    if (blockIdx.x == 0 && blockIdx.y == 0) {
        int tid = threadIdx.y * 32 + threadIdx.x;
        for (int i = tid; i < NPAR; i += 256) g_lvl[i] = -1;
        if (tid < LMAX) g_hist[tid] = 0;
        if (tid == 0) { g_barcnt = 0; g_barsense = 0; }
    }
}

// ---------------- launch 2: embed ----------------
__global__ void k_embed(const float* __restrict__ xw, const int* __restrict__ xi) {
    int n = blockIdx.x;
    int tid = threadIdx.x;   // 128
    __shared__ float s_w[LW];
    __shared__ int   s_i[LW];
    if (tid < LW) { s_w[tid] = xw[n * LW + tid]; s_i[tid] = xi[n * LW + tid]; }
    __syncthreads();
    float4 acc = make_float4(0.f, 0.f, 0.f, 0.f);
#pragma unroll 8
    for (int l = 0; l < LW; l++) {
        float4 e = ((const float4*)(g_EbuT + (size_t)s_i[l] * H))[tid];
        float w = s_w[l];
        acc.x += w * e.x; acc.y += w * e.y; acc.z += w * e.z; acc.w += w * e.w;
    }
    float4* dst = (n < NLEAF) ? (float4*)(g_nodeh + (size_t)n * H)
                              : (float4*)(g_xepar + (size_t)(n - NLEAF) * H);
    dst[tid] = acc;
}

// ---------------- launch 3: pre-GEMM (parent-id indexed) ----------------
// BM=128, BN=128, BK=32, 256 thr, 8x8
__global__ void __launch_bounds__(256) k_pregemm(
    const float* __restrict__ Wz, const float* __restrict__ bz,
    const float* __restrict__ Wr, const float* __restrict__ br,
    const float* __restrict__ Wh, const float* __restrict__ bh)
{
    __shared__ float sX[32 * 132];
    __shared__ float sW[32 * 132];
    int sel = blockIdx.z;
    const float* W    = sel == 0 ? Wz : sel == 1 ? Wr : Wh;
    const float* bias = sel == 0 ? bz : sel == 1 ? br : bh;
    float* out        = sel == 0 ? g_gz0 : sel == 1 ? g_gr0 : g_gh0;
    int m0 = blockIdx.x * 128, n0 = blockIdx.y * 128;
    int t = threadIdx.x;
    int lrow = t >> 1, lk = (t & 1) * 16;
    int ty = t >> 4, tx = t & 15;
    float acc[8][8];
#pragma unroll
    for (int i = 0; i < 8; i++)
#pragma unroll
        for (int j = 0; j < 8; j++) acc[i][j] = 0.f;
    int xm = min(m0 + lrow, NPAR - 1);
    for (int kc = 0; kc < H; kc += 32) {
        const float* xr = g_xepar + (size_t)xm * H + kc + lk;
        const float* wr = W + (size_t)(n0 + lrow) * H + kc + lk;
#pragma unroll
        for (int q = 0; q < 4; q++) {
            float4 xv = *(const float4*)(xr + q * 4);
            float4 wv = *(const float4*)(wr + q * 4);
            sX[(lk + q * 4 + 0) * 132 + lrow] = xv.x;
            sX[(lk + q * 4 + 1) * 132 + lrow] = xv.y;
            sX[(lk + q * 4 + 2) * 132 + lrow] = xv.z;
            sX[(lk + q * 4 + 3) * 132 + lrow] = xv.w;
            sW[(lk + q * 4 + 0) * 132 + lrow] = wv.x;
            sW[(lk + q * 4 + 1) * 132 + lrow] = wv.y;
            sW[(lk + q * 4 + 2) * 132 + lrow] = wv.z;
            sW[(lk + q * 4 + 3) * 132 + lrow] = wv.w;
        }
        __syncthreads();
#pragma unroll
        for (int kk = 0; kk < 32; kk++) {
            float4 a0 = *(const float4*)(sX + kk * 132 + ty * 8);
            float4 a1 = *(const float4*)(sX + kk * 132 + ty * 8 + 4);
            float4 b0 = *(const float4*)(sW + kk * 132 + tx * 8);
            float4 b1 = *(const float4*)(sW + kk * 132 + tx * 8 + 4);
            float a[8] = {a0.x,a0.y,a0.z,a0.w,a1.x,a1.y,a1.z,a1.w};
            float b[8] = {b0.x,b0.y,b0.z,b0.w,b1.x,b1.y,b1.z,b1.w};
#pragma unroll
            for (int i = 0; i < 8; i++)
#pragma unroll
                for (int j = 0; j < 8; j++) acc[i][j] += a[i] * b[j];
        }
        __syncthreads();
    }
#pragma unroll
    for (int i = 0; i < 8; i++) {
        int m = m0 + ty * 8 + i;
        if (m >= NPAR) continue;
        float* dst = out + (size_t)m * H + n0 + tx * 8;
#pragma unroll
        for (int j = 0; j < 8; j++) dst[j] = acc[i][j] + bias[n0 + tx * 8 + j];
    }
}

// ---------------- launch 4: persistent main ----------------
__device__ __forceinline__ void gridbar(int nb, int& sense) {
    __syncthreads();
    if (threadIdx.x == 0) {
        sense ^= 1;
        __threadfence();
        if (atomicAdd(&g_barcnt, 1) == nb - 1) {
            atomicExch(&g_barcnt, 0);
            __threadfence();
            g_barsense = sense;
        } else {
            while (g_barsense != sense) __nanosleep(32);
        }
        __threadfence();
    }
    __syncthreads();
}

#define AH(buf,k,head) (((buf)*4+(k))*8+(head))*65

__device__ int attn_core(int p, const int* __restrict__ tree, float* SBUF,
                         int* s_child, float* s_sc, float* s_p) {
    int tid = threadIdx.x;
    __syncthreads();
    if (tid < DEG) s_child[tid] = tree[p * DEG + tid];
    __syncthreads();
#pragma unroll
    for (int j = 0; j < 8; j++) {
        int idx = tid + j * 256;
        int k = idx >> 9, col = idx & 511, head = col >> 6, d = col & 63;
        int c = s_child[k];
        SBUF[AH(0, k, head) + d] = (c > -1) ? __ldcg(&g_nodeh[(size_t)c * H + col]) : 0.f;
    }
    __syncthreads();
    int cur = 0;
    for (int layer = 0; layer < NLAYER; layer++) {
        if (tid < 128) {
            int head = tid >> 4, q = (tid >> 2) & 3, kk = tid & 3;
            const float* hq = &SBUF[AH(cur, q, head)];
            const float* hk = &SBUF[AH(cur, kk, head)];
            float s = 0.f;
#pragma unroll
            for (int d = 0; d < DK; d++) s += hq[d] * hk[d];
            s *= 0.125f;
            if (s_child[kk] <= -1) s = -1e9f;
            s_sc[(head * 4 + q) * 4 + kk] = s;
        }
        __syncthreads();
        if (tid < 32) {
            int head = tid >> 2, q = tid & 3;
            const float* r = &s_sc[(head * 4 + q) * 4];
            float m = fmaxf(fmaxf(r[0], r[1]), fmaxf(r[2], r[3]));
            float e0 = __expf(r[0] - m), e1 = __expf(r[1] - m);
            float e2 = __expf(r[2] - m), e3 = __expf(r[3] - m);
            float inv = 1.f / (e0 + e1 + e2 + e3);
            float* pr = &s_p[(head * 4 + q) * 4];
            pr[0] = e0 * inv; pr[1] = e1 * inv; pr[2] = e2 * inv; pr[3] = e3 * inv;
        }
        __syncthreads();
        int nxt = cur ^ 1;
#pragma unroll
        for (int j = 0; j < 2; j++) {
            int col = tid + j * 256, head = col >> 6, d = col & 63;
            float v0 = SBUF[AH(cur, 0, head) + d];
            float v1 = SBUF[AH(cur, 1, head) + d];
            float v2 = SBUF[AH(cur, 2, head) + d];
            float v3 = SBUF[AH(cur, 3, head) + d];
#pragma unroll
            for (int q = 0; q < 4; q++) {
                const float* pr = &s_p[(head * 4 + q) * 4];
                SBUF[AH(nxt, q, head) + d] = pr[0] * v0 + pr[1] * v1 + pr[2] * v2 + pr[3] * v3;
            }
        }
        __syncthreads();
        cur = nxt;
    }
    return cur;
}

__device__ void phaseA(int row, const int* __restrict__ tree, float* SBUF,
                       int* s_child, float* s_sc, float* s_p) {
    int tid = threadIdx.x;
    int p = g_order[row];
    int cur = attn_core(p, tree, SBUF, s_child, s_sc, s_p);
    int cc = (s_child[0] > -1) + (s_child[1] > -1) + (s_child[2] > -1) + (s_child[3] > -1);
    float denom = (float)max(cc, 1);
#pragma unroll
    for (int j = 0; j < 2; j++) {
        int col = tid + j * 256, head = col >> 6, d = col & 63;
        float m = 0.f;
#pragma unroll
        for (int k = 0; k < DEG; k++)
            if (s_child[k] > -1) m += SBUF[AH(cur, k, head) + d];
        __stcg(&g_memv[(size_t)row * H + col], m / denom);
    }
}

// cooperative matvec path for tiny levels: one warp per (row, out-dim)
__device__ void coopB(int start, int cnt, const float* __restrict__ Uz,
                      const float* __restrict__ Ur) {
    int gw = blockIdx.x * 8 + (threadIdx.x >> 5);
    int nw = gridDim.x * 8;
    int lane = threadIdx.x & 31;
    int ntask = cnt * H;
    for (int t = gw; t < ntask; t += nw) {
        int i = t >> 9, d = t & 511;
        int row = start + i;
        const float4* mv = (const float4*)&g_memv[(size_t)row * H];
        const float4* uz = (const float4*)(Uz + (size_t)d * H);
        const float4* ur = (const float4*)(Ur + (size_t)d * H);
        float az = 0.f, ar = 0.f;
#pragma unroll
        for (int j = 0; j < 4; j++) {
            float4 m = __ldcg(&mv[lane + j * 32]);
            float4 a = __ldg(&uz[lane + j * 32]);
            az += a.x * m.x + a.y * m.y + a.z * m.z + a.w * m.w;
            float4 b = __ldg(&ur[lane + j * 32]);
            ar += b.x * m.x + b.y * m.y + b.z * m.z + b.w * m.w;
        }
#pragma unroll
        for (int o = 16; o; o >>= 1) {
            az += __shfl_down_sync(0xffffffffu, az, o);
            ar += __shfl_down_sync(0xffffffffu, ar, o);
        }
        if (lane == 0) {
            int p = g_order[row];
            size_t rb = (size_t)row * H + d;
            float z = sigf(__ldcg(&g_gz0[(size_t)p * H + d]) + az);
            float r = sigf(__ldcg(&g_gr0[(size_t)p * H + d]) + ar);
            float mem = __ldcg(&g_memv[rb]);
            __stcg(&g_zv[rb], z);
            __stcg(&g_mrv[rb], mem * r);
        }
    }
}

__device__ void coopC(int start, int cnt, const float* __restrict__ Uh) {
    int gw = blockIdx.x * 8 + (threadIdx.x >> 5);
    int nw = gridDim.x * 8;
    int lane = threadIdx.x & 31;
    int ntask = cnt * H;
    for (int t = gw; t < ntask; t += nw) {
        int i = t >> 9, d = t & 511;
        int row = start + i;
        const float4* mrv = (const float4*)&g_mrv[(size_t)row * H];
        const float4* uh = (const float4*)(Uh + (size_t)d * H);
        float ah = 0.f;
#pragma unroll
        for (int j = 0; j < 4; j++) {
            float4 m = __ldcg(&mrv[lane + j * 32]);
            float4 a = __ldg(&uh[lane + j * 32]);
            ah += a.x * m.x + a.y * m.y + a.z * m.z + a.w * m.w;
        }
#pragma unroll
        for (int o = 16; o; o >>= 1) ah += __shfl_down_sync(0xffffffffu, ah, o);
        if (lane == 0) {
            int p = g_order[row];
            size_t rb = (size_t)row * H + d;
            float c = tanhf(__ldcg(&g_gh0[(size_t)p * H + d]) + ah);
            float z = __ldcg(&g_zv[rb]);
            float mem = __ldcg(&g_memv[rb]);
            __stcg(&g_nodeh[(size_t)(NLEAF + p) * H + d], z * mem + (1.f - z) * c);
        }
    }
}

// GEMM tile phases: BM=32, BN in {32,64}
template<int BN>
__device__ void phaseB(int start, int cnt, int t,
                       const float* __restrict__ Uz, const float* __restrict__ Ur,
                       float* SBUF, int* s_pid) {
    const int NT = H / BN;
    int m0 = (t / NT) * 32, n0 = (t % NT) * BN;
    float* sA  = SBUF;
    float* sWz = SBUF + 1056;
    float* sWr = SBUF + 1056 + 32 * (BN + 1);
    int tid = threadIdx.x;
    const int TX = BN / 4;         // 16 or 8
    const int RM = BN / 32;        // 2 or 1
    int ty = tid / TX, tx = tid % TX;
    int am = tid >> 3, ak = (tid & 7) * 4;
    float az[RM][4], ar[RM][4];
#pragma unroll
    for (int i = 0; i < RM; i++)
#pragma unroll
        for (int j = 0; j < 4; j++) { az[i][j] = 0.f; ar[i][j] = 0.f; }
    __syncthreads();
    if (tid < 32) s_pid[tid] = g_order[start + min(m0 + tid, cnt - 1)];
    int rrow = start + ((m0 + am < cnt) ? m0 + am : 0);
    for (int kc = 0; kc < H; kc += 32) {
        float4 a = __ldcg((const float4*)&g_memv[(size_t)rrow * H + kc + ak]);
        sA[(ak + 0) * 33 + am] = a.x; sA[(ak + 1) * 33 + am] = a.y;
        sA[(ak + 2) * 33 + am] = a.z; sA[(ak + 3) * 33 + am] = a.w;
        if (BN == 64) {
            int wn = tid >> 2, wk = (tid & 3) * 8;
            const float* wz = Uz + (size_t)(n0 + wn) * H + kc + wk;
            const float* wr = Ur + (size_t)(n0 + wn) * H + kc + wk;
#pragma unroll
            for (int q = 0; q < 2; q++) {
                float4 zv = *(const float4*)(wz + q * 4);
                float4 rv = *(const float4*)(wr + q * 4);
                sWz[(wk + q * 4 + 0) * (BN + 1) + wn] = zv.x;
                sWz[(wk + q * 4 + 1) * (BN + 1) + wn] = zv.y;
                sWz[(wk + q * 4 + 2) * (BN + 1) + wn] = zv.z;
                sWz[(wk + q * 4 + 3) * (BN + 1) + wn] = zv.w;
                sWr[(wk + q * 4 + 0) * (BN + 1) + wn] = rv.x;
                sWr[(wk + q * 4 + 1) * (BN + 1) + wn] = rv.y;
                sWr[(wk + q * 4 + 2) * (BN + 1) + wn] = rv.z;
                sWr[(wk + q * 4 + 3) * (BN + 1) + wn] = rv.w;
            }
        } else {
            int wn = tid >> 3, wk = (tid & 7) * 4;
            float4 zv = *(const float4*)(Uz + (size_t)(n0 + wn) * H + kc + wk);
            float4 rv = *(const float4*)(Ur + (size_t)(n0 + wn) * H + kc + wk);
            sWz[(wk + 0) * (BN + 1) + wn] = zv.x; sWz[(wk + 1) * (BN + 1) + wn] = zv.y;
            sWz[(wk + 2) * (BN + 1) + wn] = zv.z; sWz[(wk + 3) * (BN + 1) + wn] = zv.w;
            sWr[(wk + 0) * (BN + 1) + wn] = rv.x; sWr[(wk + 1) * (BN + 1) + wn] = rv.y;
            sWr[(wk + 2) * (BN + 1) + wn] = rv.z; sWr[(wk + 3) * (BN + 1) + wn] = rv.w;
        }
        __syncthreads();
#pragma unroll
        for (int kk = 0; kk < 32; kk++) {
            float a[RM];
#pragma unroll
            for (int i = 0; i < RM; i++) a[i] = sA[kk * 33 + ty * RM + i];
#pragma unroll
            for (int n = 0; n < 4; n++) {
                float bz = sWz[kk * (BN + 1) + tx * 4 + n];
                float br = sWr[kk * (BN + 1) + tx * 4 + n];
#pragma unroll
                for (int i = 0; i < RM; i++) {
                    az[i][n] += a[i] * bz;
                    ar[i][n] += a[i] * br;
                }
            }
        }
        __syncthreads();
    }
#pragma unroll
    for (int mi = 0; mi < RM; mi++) {
        int m = m0 + ty * RM + mi;
        if (m >= cnt) continue;
        int p = s_pid[ty * RM + mi];
        size_t rb = (size_t)(start + m) * H + n0 + tx * 4;
        size_t pb = (size_t)p * H + n0 + tx * 4;
#pragma unroll
        for (int n = 0; n < 4; n++) {
            float z = sigf(__ldcg(&g_gz0[pb + n]) + az[mi][n]);
            float r = sigf(__ldcg(&g_gr0[pb + n]) + ar[mi][n]);
            float mem = __ldcg(&g_memv[rb + n]);
            __stcg(&g_zv[rb + n], z);
            __stcg(&g_mrv[rb + n], mem * r);
        }
    }
}

template<int BN>
__device__ void phaseC(int start, int cnt, int t,
                       const float* __restrict__ Uh, float* SBUF, int* s_pid) {
    const int NT = H / BN;
    int m0 = (t / NT) * 32, n0 = (t % NT) * BN;
    float* sA = SBUF;
    float* sW = SBUF + 1056;
    int tid = threadIdx.x;
    const int TX = BN / 4;
    const int RM = BN / 32;
    int ty = tid / TX, tx = tid % TX;
    int am = tid >> 3, ak = (tid & 7) * 4;
    float ah[RM][4];
#pragma unroll
    for (int i = 0; i < RM; i++)
#pragma unroll
        for (int j = 0; j < 4; j++) ah[i][j] = 0.f;
    __syncthreads();
    if (tid < 32) s_pid[tid] = g_order[start + min(m0 + tid, cnt - 1)];
    int rrow = start + ((m0 + am < cnt) ? m0 + am : 0);
    for (int kc = 0; kc < H; kc += 32) {
        float4 a = __ldcg((const float4*)&g_mrv[(size_t)rrow * H + kc + ak]);
        sA[(ak + 0) * 33 + am] = a.x; sA[(ak + 1) * 33 + am] = a.y;
        sA[(ak + 2) * 33 + am] = a.z; sA[(ak + 3) * 33 + am] = a.w;
        if (BN == 64) {
            int wn = tid >> 2, wk = (tid & 3) * 8;
            const float* wh = Uh + (size_t)(n0 + wn) * H + kc + wk;
#pragma unroll
            for (int q = 0; q < 2; q++) {
                float4 hv = *(const float4*)(wh + q * 4);
                sW[(wk + q * 4 + 0) * (BN + 1) + wn] = hv.x;
                sW[(wk + q * 4 + 1) * (BN + 1) + wn] = hv.y;
                sW[(wk + q * 4 + 2) * (BN + 1) + wn] = hv.z;
                sW[(wk + q * 4 + 3) * (BN + 1) + wn] = hv.w;
            }
        } else {
            int wn = tid >> 3, wk = (tid & 7) * 4;
            float4 hv = *(const float4*)(Uh + (size_t)(n0 + wn) * H + kc + wk);
            sW[(wk + 0) * (BN + 1) + wn] = hv.x; sW[(wk + 1) * (BN + 1) + wn] = hv.y;
            sW[(wk + 2) * (BN + 1) + wn] = hv.z; sW[(wk + 3) * (BN + 1) + wn] = hv.w;
        }
        __syncthreads();
#pragma unroll
        for (int kk = 0; kk < 32; kk++) {
            float a[RM];
#pragma unroll
            for (int i = 0; i < RM; i++) a[i] = sA[kk * 33 + ty * RM + i];
#pragma unroll
            for (int n = 0; n < 4; n++) {
                float b = sW[kk * (BN + 1) + tx * 4 + n];
#pragma unroll
                for (int i = 0; i < RM; i++) ah[i][n] += a[i] * b;
            }
        }
        __syncthreads();
    }
#pragma unroll
    for (int mi = 0; mi < RM; mi++) {
        int m = m0 + ty * RM + mi;
        if (m >= cnt) continue;
        int p = s_pid[ty * RM + mi];
        size_t rb = (size_t)(start + m) * H + n0 + tx * 4;
        size_t pb = (size_t)p * H + n0 + tx * 4;
#pragma unroll
        for (int n = 0; n < 4; n++) {
            float c = tanhf(__ldcg(&g_gh0[pb + n]) + ah[mi][n]);
            float z = __ldcg(&g_zv[rb + n]);
            float mem = __ldcg(&g_memv[rb + n]);
            __stcg(&g_nodeh[(size_t)(NLEAF + p) * H + n0 + tx * 4 + n],
                   z * mem + (1.f - z) * c);
        }
    }
}

__global__ void __launch_bounds__(256) k_main(
    const int* __restrict__ tree,
    const float* __restrict__ Uz, const float* __restrict__ Ur,
    const float* __restrict__ Uh)
{
    __shared__ float SBUF[5696];
    __shared__ float s_sc[128], s_p[128];
    __shared__ int s_child[DEG], s_pid[32];
    int nb = gridDim.x;
    int sense = 0;
    int tid = threadIdx.x;
    int gstride = nb * 256;

    // ---- leveling (dataflow spin; every parent has its own thread) ----
    for (int p = blockIdx.x * 256 + tid; p < NPAR; p += gstride) {
        int lv = 0;
#pragma unroll
        for (int k = 0; k < DEG; k++) {
            int c = tree[p * DEG + k];
            if (c >= NLEAF) {
                int v;
                while ((v = atomicAdd(&g_lvl[c - NLEAF], 0)) < 0) __nanosleep(40);
                lv = max(lv, v + 1);
            }
        }
        if (lv > LMAX - 1) lv = LMAX - 1;
        atomicExch(&g_lvl[p], lv);
    }
    gridbar(nb, sense);
    for (int p = blockIdx.x * 256 + tid; p < NPAR; p += gstride)
        atomicAdd(&g_hist[g_lvl[p]], 1);
    gridbar(nb, sense);
    if (blockIdx.x == 0 && tid == 0) {
        int acc = 0, nl = 1;
        for (int i = 0; i < LMAX; i++) {
            g_lstart[i] = acc; g_lofs[i] = acc;
            acc += g_hist[i];
            if (g_hist[i] > 0) nl = i + 1;
        }
        g_nlev = nl;
    }
    gridbar(nb, sense);
    for (int p = blockIdx.x * 256 + tid; p < NPAR; p += gstride)
        g_order[atomicAdd(&g_lofs[g_lvl[p]], 1)] = p;
    gridbar(nb, sense);

    int nlev = g_nlev;
    for (int l = 0; l < nlev; l++) {
        int start = g_lstart[l], cnt = g_hist[l];
        if (cnt == 0) continue;
        for (int j = blockIdx.x; j < cnt; j += nb)
            phaseA(start + j, tree, SBUF, s_child, s_sc, s_p);
        gridbar(nb, sense);
        if (cnt < 32) {
            coopB(start, cnt, Uz, Ur);
            gridbar(nb, sense);
            coopC(start, cnt, Uh);
            gridbar(nb, sense);
        } else {
            int mt = (cnt + 31) >> 5;
            if (mt * 8 >= nb) {
                int nt = mt * 8;
                for (int t = blockIdx.x; t < nt; t += nb)
                    phaseB<64>(start, cnt, t, Uz, Ur, SBUF, s_pid);
                gridbar(nb, sense);
                for (int t = blockIdx.x; t < nt; t += nb)
                    phaseC<64>(start, cnt, t, Uh, SBUF, s_pid);
            } else {
                int nt = mt * 16;
                for (int t = blockIdx.x; t < nt; t += nb)
                    phaseB<32>(start, cnt, t, Uz, Ur, SBUF, s_pid);
                gridbar(nb, sense);
                for (int t = blockIdx.x; t < nt; t += nb)
                    phaseC<32>(start, cnt, t, Uh, SBUF, s_pid);
            }
            gridbar(nb, sense);
        }
    }
}

// ---------------- reductions ----------------
__global__ void k_redmax() {
    int tid = threadIdx.x;
    int b = blockIdx.x;
    const float* base = g_nodeh + (size_t)NLEAF * H;
    float m = -3.4e38f;
    for (int p = b * RED_CHUNK; p < (b + 1) * RED_CHUNK; p++)
        m = fmaxf(m, base[(size_t)p * H + tid]);
    g_pmax[b * H + tid] = m;
}

__global__ void k_final(const float* __restrict__ Wo, const float* __restrict__ bo,
                        float* __restrict__ out) {
    __shared__ float s_f[H];
    __shared__ float s_logit[NCLASS];
    int tid = threadIdx.x;   // 512
    float m = g_pmax[tid];
    for (int b = 1; b < NB_RED; b++) m = fmaxf(m, g_pmax[b * H + tid]);
    s_f[tid] = m;
    __syncthreads();
    int w = tid >> 5, lane = tid & 31;
    if (w < NCLASS) {
        float acc = 0.f;
        for (int j = lane; j < H; j += 32) acc += Wo[w * H + j] * s_f[j];
#pragma unroll
        for (int o = 16; o; o >>= 1) acc += __shfl_down_sync(0xffffffffu, acc, o);
        if (lane == 0) s_logit[w] = acc + bo[w];
    }
    __syncthreads();
    if (tid == 0) {
        float mx = s_logit[0];
        for (int i = 1; i < NCLASS; i++) mx = fmaxf(mx, s_logit[i]);
        float e[NCLASS], s = 0.f;
        for (int i = 0; i < NCLASS; i++) { e[i] = __expf(s_logit[i] - mx); s += e[i]; }
        for (int i = 0; i < NCLASS; i++) out[i] = e[i] / s;
    }
}

extern "C" void kernel_launch(void* const* d_in, const int* in_sizes, int n_in,
                              void* d_out, int out_size) {
    const float* x_word  = (const float*)d_in[0];
    const int*   x_index = (const int*)  d_in[1];
    const int*   tree    = (const int*)  d_in[2];
    const float* E_bu    = (const float*)d_in[3];
    const float* W_z = (const float*)d_in[4];
    const float* U_z = (const float*)d_in[5];
    const float* b_z = (const float*)d_in[6];
    const float* W_r = (const float*)d_in[7];
    const float* U_r = (const float*)d_in[8];
    const float* b_r = (const float*)d_in[9];
    const float* W_h = (const float*)d_in[10];
    const float* U_h = (const float*)d_in[11];
    const float* b_h = (const float*)d_in[12];
    const float* W_out = (const float*)d_in[13];
    const float* b_out = (const float*)d_in[14];
    float* out = (float*)d_out;

    static int nb_main = 0;
    if (nb_main == 0) {
        int dev = 0; cudaGetDevice(&dev);
        int nsm = 0; cudaDeviceGetAttribute(&nsm, cudaDevAttrMultiProcessorCount, dev);
        int perSM = 0;
        cudaOccupancyMaxActiveBlocksPerMultiprocessor(&perSM, k_main, 256, 0);
        if (perSM < 1) perSM = 1;
        nb_main = nsm * perSM;
    }

    dim3 tb(32, 8), tg((VOCAB + 31) / 32, H / 32);
    k_setup<<<tg, tb>>>(E_bu);
    k_embed<<<NTOT, 128>>>(x_word, x_index);
    k_pregemm<<<dim3((NPAR + 127) / 128, H / 128, 3), 256>>>(W_z, b_z, W_r, b_r, W_h, b_h);
    k_main<<<nb_main, 256>>>(tree, U_z, U_r, U_h);
    k_redmax<<<NB_RED, H>>>();
    k_final<<<1, H>>>(W_out, b_out, out);
}